// round 1
// baseline (speedup 1.0000x reference)
#include <cuda_runtime.h>
#include <math.h>

#define B_  512
#define S_  200
#define H_  256
#define K_  16
#define ROWS (B_ * S_)      // 102400
#define TM  64              // rows per block in MLP kernel
#define XS_STRIDE 260       // padded row stride (floats): 260*4 % 16 == 0, bank-safe

// scratch: masked, K-softmaxed, scaled logits, shape (B*S, K)
__device__ float g_A[ROWS * K_];

// ---------------------------------------------------------------------------
// One dense layer: out_s[r][c] = relu( sum_k in_s[r][k] * Wg[k][c] + bg[c] )
// Thread owns 16 rows x 4 cols. in_s/out_s are smem tiles with XS_STRIDE.
// ---------------------------------------------------------------------------
__device__ __forceinline__ void mlp_layer(const float* __restrict__ in_s,
                                          const float* __restrict__ Wg,
                                          const float* __restrict__ bg,
                                          float* __restrict__ out_s,
                                          int r0, int c0)
{
    const float4 bv = *(const float4*)&bg[c0];
    float acc[16][4];
#pragma unroll
    for (int r = 0; r < 16; r++) {
        acc[r][0] = bv.x; acc[r][1] = bv.y; acc[r][2] = bv.z; acc[r][3] = bv.w;
    }

#pragma unroll 2
    for (int k = 0; k < H_; k += 4) {
        const float4 w0 = __ldg((const float4*)&Wg[(k + 0) * H_ + c0]);
        const float4 w1 = __ldg((const float4*)&Wg[(k + 1) * H_ + c0]);
        const float4 w2 = __ldg((const float4*)&Wg[(k + 2) * H_ + c0]);
        const float4 w3 = __ldg((const float4*)&Wg[(k + 3) * H_ + c0]);
#pragma unroll
        for (int r = 0; r < 16; r++) {
            const float4 xv = *(const float4*)&in_s[(r0 + r) * XS_STRIDE + k];
            acc[r][0] += xv.x * w0.x; acc[r][1] += xv.x * w0.y;
            acc[r][2] += xv.x * w0.z; acc[r][3] += xv.x * w0.w;
            acc[r][0] += xv.y * w1.x; acc[r][1] += xv.y * w1.y;
            acc[r][2] += xv.y * w1.z; acc[r][3] += xv.y * w1.w;
            acc[r][0] += xv.z * w2.x; acc[r][1] += xv.z * w2.y;
            acc[r][2] += xv.z * w2.z; acc[r][3] += xv.z * w2.w;
            acc[r][0] += xv.w * w3.x; acc[r][1] += xv.w * w3.y;
            acc[r][2] += xv.w * w3.z; acc[r][3] += xv.w * w3.w;
        }
    }

#pragma unroll
    for (int r = 0; r < 16; r++) {
        float4 o;
        o.x = fmaxf(acc[r][0], 0.0f);
        o.y = fmaxf(acc[r][1], 0.0f);
        o.z = fmaxf(acc[r][2], 0.0f);
        o.w = fmaxf(acc[r][3], 0.0f);
        *(float4*)&out_s[(r0 + r) * XS_STRIDE + c0] = o;
    }
}

// ---------------------------------------------------------------------------
// Kernel 1: fused MLP (2 layers) + logits + softmax over K + mask + /sqrt(K)
// grid = ROWS/TM blocks, 256 threads.
// ---------------------------------------------------------------------------
__global__ __launch_bounds__(256, 1)
void mlp_softk_kernel(const float* __restrict__ X,
                      const int*   __restrict__ mask,
                      const float* __restrict__ W1, const float* __restrict__ b1,
                      const float* __restrict__ W2, const float* __restrict__ b2,
                      const float* __restrict__ W3)
{
    extern __shared__ float smem[];
    float* Xs = smem;                       // [TM][XS_STRIDE]
    float* Hs = smem + TM * XS_STRIDE;      // [TM][XS_STRIDE]

    const int tid  = threadIdx.x;
    const int row0 = blockIdx.x * TM;

    // load input tile (coalesced float4)
    for (int idx = tid; idx < TM * (H_ / 4); idx += 256) {
        const int r  = idx >> 6;
        const int c4 = idx & 63;
        const float4 v = ((const float4*)(X + (size_t)(row0 + r) * H_))[c4];
        *(float4*)&Xs[r * XS_STRIDE + c4 * 4] = v;
    }
    __syncthreads();

    const int tx = tid & 63;
    const int ty = tid >> 6;
    const int c0 = tx * 4;
    const int r0 = ty * 16;

    // layer 1: Hs = relu(Xs @ W1 + b1)
    mlp_layer(Xs, W1, b1, Hs, r0, c0);
    __syncthreads();
    // layer 2: Xs = relu(Hs @ W2 + b2)   (Xs reused as h2)
    mlp_layer(Hs, W2, b2, Xs, r0, c0);
    __syncthreads();

    // logits + softmax over K=16. Thread -> (row rr, 4 cols kq*4..kq*4+3).
    {
        const int rr = tid >> 2;   // 0..63
        const int kq = tid & 3;    // 0..3
        float a0 = 0.f, a1 = 0.f, a2 = 0.f, a3 = 0.f;
#pragma unroll 2
        for (int k = 0; k < H_; k += 4) {
            const float4 xv = *(const float4*)&Xs[rr * XS_STRIDE + k];
            const float4 wa = __ldg((const float4*)&W3[(k + 0) * K_ + kq * 4]);
            const float4 wb = __ldg((const float4*)&W3[(k + 1) * K_ + kq * 4]);
            const float4 wc = __ldg((const float4*)&W3[(k + 2) * K_ + kq * 4]);
            const float4 wd = __ldg((const float4*)&W3[(k + 3) * K_ + kq * 4]);
            a0 += xv.x * wa.x + xv.y * wb.x + xv.z * wc.x + xv.w * wd.x;
            a1 += xv.x * wa.y + xv.y * wb.y + xv.z * wc.y + xv.w * wd.y;
            a2 += xv.x * wa.z + xv.y * wb.z + xv.z * wc.z + xv.w * wd.z;
            a3 += xv.x * wa.w + xv.y * wb.w + xv.z * wc.w + xv.w * wd.w;
        }
        // softmax over the 16 logits held by the 4-lane group {rr}
        float m = fmaxf(fmaxf(a0, a1), fmaxf(a2, a3));
        m = fmaxf(m, __shfl_xor_sync(0xffffffffu, m, 1));
        m = fmaxf(m, __shfl_xor_sync(0xffffffffu, m, 2));
        const float e0 = expf(a0 - m), e1 = expf(a1 - m);
        const float e2 = expf(a2 - m), e3 = expf(a3 - m);
        float ssum = e0 + e1 + e2 + e3;
        ssum += __shfl_xor_sync(0xffffffffu, ssum, 1);
        ssum += __shfl_xor_sync(0xffffffffu, ssum, 2);
        const float inv = 0.25f / ssum;           // includes / sqrt(K) = /4

        const int row = row0 + rr;
        const bool mk = (mask[row] != 0);
        float4 o;
        o.x = mk ? e0 * inv : -2500.0f;           // -10000/4
        o.y = mk ? e1 * inv : -2500.0f;
        o.z = mk ? e2 * inv : -2500.0f;
        o.w = mk ? e3 * inv : -2500.0f;
        ((float4*)&g_A[(size_t)row * K_])[kq] = o;
    }
}

// ---------------------------------------------------------------------------
// Kernel 2 (one block per batch b): softmax over S per k, * time factor,
// then out[b,k,h] = sum_s X[b,s,h] * D[b,s,k].  256 threads, thread = h.
// ---------------------------------------------------------------------------
__global__ __launch_bounds__(256, 2)
void softs_out_kernel(const float* __restrict__ X,
                      const float* __restrict__ tf,
                      float*       __restrict__ out)
{
    __shared__ float As[S_ * K_];    // 12.8 KB
    __shared__ float Tf[S_];
    __shared__ float Mk[K_], Ik[K_];

    const int b   = blockIdx.x;
    const int tid = threadIdx.x;

    for (int idx = tid; idx < S_ * K_; idx += 256)
        As[idx] = g_A[(size_t)b * S_ * K_ + idx];
    for (int idx = tid; idx < S_; idx += 256)
        Tf[idx] = tf[b * S_ + idx];
    __syncthreads();

    const int warp = tid >> 5, lane = tid & 31;
    for (int k = warp; k < K_; k += 8) {
        float m = -1e30f;
        for (int s = lane; s < S_; s += 32) m = fmaxf(m, As[s * K_ + k]);
#pragma unroll
        for (int o = 16; o; o >>= 1) m = fmaxf(m, __shfl_xor_sync(0xffffffffu, m, o));
        float ssum = 0.0f;
        for (int s = lane; s < S_; s += 32) ssum += expf(As[s * K_ + k] - m);
#pragma unroll
        for (int o = 16; o; o >>= 1) ssum += __shfl_xor_sync(0xffffffffu, ssum, o);
        if (lane == 0) { Mk[k] = m; Ik[k] = 1.0f / ssum; }
    }
    __syncthreads();

    // normalize in place, fold in time factor
    for (int idx = tid; idx < S_ * K_; idx += 256) {
        const int s = idx >> 4, k = idx & 15;
        As[idx] = expf(As[idx] - Mk[k]) * Ik[k] * Tf[s];
    }
    __syncthreads();

    // out[b][k][tid] = sum_s X[b][s][tid] * As[s][k]
    float acc[K_];
#pragma unroll
    for (int k = 0; k < K_; k++) acc[k] = 0.0f;

    const float* Xb = X + (size_t)b * S_ * H_;
#pragma unroll 2
    for (int s = 0; s < S_; s++) {
        const float xv = __ldg(&Xb[s * H_ + tid]);
        const float4* d4 = (const float4*)&As[s * K_];
        const float4 d0 = d4[0], d1 = d4[1], d2 = d4[2], d3 = d4[3];
        acc[0]  += xv * d0.x; acc[1]  += xv * d0.y; acc[2]  += xv * d0.z; acc[3]  += xv * d0.w;
        acc[4]  += xv * d1.x; acc[5]  += xv * d1.y; acc[6]  += xv * d1.z; acc[7]  += xv * d1.w;
        acc[8]  += xv * d2.x; acc[9]  += xv * d2.y; acc[10] += xv * d2.z; acc[11] += xv * d2.w;
        acc[12] += xv * d3.x; acc[13] += xv * d3.y; acc[14] += xv * d3.z; acc[15] += xv * d3.w;
    }

    float* ob = out + (size_t)b * K_ * H_;
#pragma unroll
    for (int k = 0; k < K_; k++) ob[k * H_ + tid] = acc[k];
}

// ---------------------------------------------------------------------------
extern "C" void kernel_launch(void* const* d_in, const int* in_sizes, int n_in,
                              void* d_out, int out_size)
{
    const float* X    = (const float*)d_in[0];   // (B,S,H)
    const int*   mask = (const int*)  d_in[1];   // (B,S,1) bool -> int32
    const float* tf   = (const float*)d_in[2];   // (B,S,1)
    const float* W1   = (const float*)d_in[3];
    const float* b1   = (const float*)d_in[4];
    const float* W2   = (const float*)d_in[5];
    const float* b2   = (const float*)d_in[6];
    const float* W3   = (const float*)d_in[7];
    float* out = (float*)d_out;                  // (B,K,H)

    const size_t smem1 = (size_t)2 * TM * XS_STRIDE * sizeof(float); // 133120 B
    cudaFuncSetAttribute(mlp_softk_kernel,
                         cudaFuncAttributeMaxDynamicSharedMemorySize, (int)smem1);

    mlp_softk_kernel<<<ROWS / TM, 256, smem1>>>(X, mask, W1, b1, W2, b2, W3);
    softs_out_kernel<<<B_, 256>>>(X, tf, out);
}

// round 3
// speedup vs baseline: 2.7174x; 2.7174x over previous
#include <cuda_runtime.h>
#include <math.h>
#include <stdint.h>

#define B_  512
#define S_  200
#define H_  256
#define K_  16
#define ROWS (B_*S_)          // 102400
#define TM  128               // rows per CTA
#define NBLK (ROWS/TM)        // 800

#define AST 260               // A smem row stride (floats); 260 % 32 == 4
#define BST 68                // B smem row stride (floats); 68 % 32 == 4
#define A_FLOATS (128*AST)    // 33280
#define SM_BYTES ((A_FLOATS + 256*BST)*4)   // 202752 B

// scratch: masked, K-softmaxed, scaled logits (B*S, K)
__device__ float g_A[ROWS * K_];

__device__ __forceinline__ uint32_t f2tf32(float x) {   // round-to-nearest tf32
    uint32_t r; asm("cvt.rna.tf32.f32 %0, %1;" : "=r"(r) : "f"(x)); return r;
}
__device__ __forceinline__ void mma8(float c[4], const uint32_t a[4],
                                     uint32_t b0, uint32_t b1) {
    asm("mma.sync.aligned.m16n8k8.row.col.f32.tf32.tf32.f32 "
        "{%0,%1,%2,%3}, {%4,%5,%6,%7}, {%8,%9}, {%0,%1,%2,%3};"
        : "+f"(c[0]), "+f"(c[1]), "+f"(c[2]), "+f"(c[3])
        : "r"(a[0]), "r"(a[1]), "r"(a[2]), "r"(a[3]), "r"(b0), "r"(b1));
}

// ---------------------------------------------------------------------------
// Kernel 1: tf32 mma.sync MLP (2 layers) + logits + K-softmax + mask + /4
// grid = 800, block = 256 (8 warps; warp grid 4(M) x 2(N) for layers 1-2)
// ---------------------------------------------------------------------------
__global__ __launch_bounds__(256, 1)
void mlp_softk_kernel(const float* __restrict__ X,
                      const int*   __restrict__ mask,
                      const float* __restrict__ W1, const float* __restrict__ b1,
                      const float* __restrict__ W2, const float* __restrict__ b2,
                      const float* __restrict__ W3)
{
    extern __shared__ float sm[];
    uint32_t* Au = (uint32_t*)sm;                 // A tile: 128 x 256 tf32, stride AST
    uint32_t* Bu = (uint32_t*)(sm + A_FLOATS);    // B tile: 256 x 64 tf32, stride BST

    const int tid  = threadIdx.x;
    const int wid  = tid >> 5;
    const int lane = tid & 31;
    const int g    = lane >> 2;    // group id (0..7)
    const int tq   = lane & 3;     // thread-in-group
    const int row0 = blockIdx.x * TM;

    // ---- load X tile -> A (tf32-rna) ----
    #pragma unroll 4
    for (int it = 0; it < 32; it++) {
        const int idx = tid + it * 256;
        const int r = idx >> 6, c4 = (idx & 63) * 4;
        const float4 v = __ldg((const float4*)(X + (size_t)(row0 + r) * H_ + c4));
        uint4 o;
        o.x = f2tf32(v.x); o.y = f2tf32(v.y); o.z = f2tf32(v.z); o.w = f2tf32(v.w);
        *(uint4*)&Au[r * AST + c4] = o;
    }

    const int wm = wid & 3;        // M block: rows wm*32 .. +31
    const int wn = wid >> 2;       // N half:  cols wn*128 .. +127

    // ---- layers 1 & 2 ----
    #pragma unroll 1
    for (int layer = 0; layer < 2; layer++) {
        const float* Wg = layer ? W2 : W1;
        const float* bg = layer ? b2 : b1;

        float acc[2][16][4];
        #pragma unroll
        for (int mt = 0; mt < 2; mt++)
            #pragma unroll
            for (int n8 = 0; n8 < 16; n8++)
                #pragma unroll
                for (int i = 0; i < 4; i++) acc[mt][n8][i] = 0.0f;

        #pragma unroll 1
        for (int kc = 0; kc < 4; kc++) {
            __syncthreads();   // prior users of A/B done (incl. X load on first pass)
            // load W chunk transposed: Bu[n=tid][kl=0..63]
            #pragma unroll 4
            for (int it = 0; it < 16; it++) {
                const int kg = kc * 64 + it * 4;
                uint4 o;
                o.x = f2tf32(__ldg(&Wg[(size_t)(kg + 0) * H_ + tid]));
                o.y = f2tf32(__ldg(&Wg[(size_t)(kg + 1) * H_ + tid]));
                o.z = f2tf32(__ldg(&Wg[(size_t)(kg + 2) * H_ + tid]));
                o.w = f2tf32(__ldg(&Wg[(size_t)(kg + 3) * H_ + tid]));
                *(uint4*)&Bu[tid * BST + it * 4] = o;
            }
            __syncthreads();

            #pragma unroll
            for (int ks = 0; ks < 8; ks++) {
                const int k0 = kc * 64 + ks * 8;    // col in A
                const int kl = ks * 8;              // col in B chunk
                uint32_t a[2][4];
                #pragma unroll
                for (int mt = 0; mt < 2; mt++) {
                    const int r = wm * 32 + mt * 16 + g;
                    a[mt][0] = Au[(r    ) * AST + k0 + tq];
                    a[mt][1] = Au[(r + 8) * AST + k0 + tq];
                    a[mt][2] = Au[(r    ) * AST + k0 + tq + 4];
                    a[mt][3] = Au[(r + 8) * AST + k0 + tq + 4];
                }
                #pragma unroll
                for (int n8 = 0; n8 < 16; n8++) {
                    const int n = wn * 128 + n8 * 8 + g;
                    const uint32_t b0 = Bu[n * BST + kl + tq];
                    const uint32_t b1 = Bu[n * BST + kl + tq + 4];
                    mma8(acc[0][n8], a[0], b0, b1);
                    mma8(acc[1][n8], a[1], b0, b1);
                }
            }
        }
        __syncthreads();   // all mma reads of A done -> safe to overwrite A

        // epilogue: bias + relu + tf32 -> A
        #pragma unroll
        for (int mt = 0; mt < 2; mt++) {
            const int r = wm * 32 + mt * 16 + g;
            #pragma unroll
            for (int n8 = 0; n8 < 16; n8++) {
                const int c = wn * 128 + n8 * 8 + 2 * tq;
                const float2 bb = *(const float2*)&bg[c];
                uint2 o0, o1;
                o0.x = f2tf32(fmaxf(acc[mt][n8][0] + bb.x, 0.f));
                o0.y = f2tf32(fmaxf(acc[mt][n8][1] + bb.y, 0.f));
                o1.x = f2tf32(fmaxf(acc[mt][n8][2] + bb.x, 0.f));
                o1.y = f2tf32(fmaxf(acc[mt][n8][3] + bb.y, 0.f));
                *(uint2*)&Au[(r    ) * AST + c] = o0;
                *(uint2*)&Au[(r + 8) * AST + c] = o1;
            }
        }
    }

    // ---- layer 3: logits = h2 @ W3 (N=16, full K in smem) ----
    __syncthreads();   // epilogue writes of layer-2 visible; B free
    {
        const int k = tid;   // 0..255
        const float4* w3r = (const float4*)(W3 + (size_t)k * K_);
        #pragma unroll
        for (int q = 0; q < 4; q++) {
            const float4 v = __ldg(&w3r[q]);
            Bu[(q * 4 + 0) * AST + k] = f2tf32(v.x);
            Bu[(q * 4 + 1) * AST + k] = f2tf32(v.y);
            Bu[(q * 4 + 2) * AST + k] = f2tf32(v.z);
            Bu[(q * 4 + 3) * AST + k] = f2tf32(v.w);
        }
    }
    __syncthreads();

    float acc3[2][4];
    #pragma unroll
    for (int n8 = 0; n8 < 2; n8++)
        #pragma unroll
        for (int i = 0; i < 4; i++) acc3[n8][i] = 0.0f;

    {
        const int r = wid * 16 + g;   // each warp: 16 rows
        #pragma unroll 4
        for (int ks = 0; ks < 32; ks++) {
            const int k0 = ks * 8;
            uint32_t a[4];
            a[0] = Au[(r    ) * AST + k0 + tq];
            a[1] = Au[(r + 8) * AST + k0 + tq];
            a[2] = Au[(r    ) * AST + k0 + tq + 4];
            a[3] = Au[(r + 8) * AST + k0 + tq + 4];
            #pragma unroll
            for (int n8 = 0; n8 < 2; n8++) {
                const uint32_t b0 = Bu[(n8 * 8 + g) * AST + k0 + tq];
                const uint32_t b1 = Bu[(n8 * 8 + g) * AST + k0 + tq + 4];
                mma8(acc3[n8], a, b0, b1);
            }
        }
    }

    // ---- softmax over K=16 per row, mask, /4, store ----
    // thread holds rows r, r+8; per row 4 logits: cols 2tq,2tq+1,2tq+8,2tq+9
    #pragma unroll
    for (int p = 0; p < 2; p++) {   // p=0: row r ; p=1: row r+8
        const int row = row0 + wid * 16 + g + p * 8;
        float v0 = acc3[0][2 * p], v1 = acc3[0][2 * p + 1];
        float v2 = acc3[1][2 * p], v3 = acc3[1][2 * p + 1];
        float m = fmaxf(fmaxf(v0, v1), fmaxf(v2, v3));
        m = fmaxf(m, __shfl_xor_sync(0xffffffffu, m, 1));
        m = fmaxf(m, __shfl_xor_sync(0xffffffffu, m, 2));
        const float e0 = expf(v0 - m), e1 = expf(v1 - m);
        const float e2 = expf(v2 - m), e3 = expf(v3 - m);
        float ssum = e0 + e1 + e2 + e3;
        ssum += __shfl_xor_sync(0xffffffffu, ssum, 1);
        ssum += __shfl_xor_sync(0xffffffffu, ssum, 2);
        const float inv = 0.25f / ssum;             // includes /sqrt(K) = /4
        const bool mk = (mask[row] != 0);
        float2 oa, ob;
        oa.x = mk ? e0 * inv : -2500.0f;            // -10000/4
        oa.y = mk ? e1 * inv : -2500.0f;
        ob.x = mk ? e2 * inv : -2500.0f;
        ob.y = mk ? e3 * inv : -2500.0f;
        *(float2*)&g_A[(size_t)row * K_ + 2 * tq]     = oa;
        *(float2*)&g_A[(size_t)row * K_ + 8 + 2 * tq] = ob;
    }
}

// ---------------------------------------------------------------------------
// Kernel 2: softmax over S per (b,k), * time factor, out[b,k,h] = sum_s X*D
// grid = (512, 2); f32x2 packed FMA (family-generic PTX, verified compiles).
// ---------------------------------------------------------------------------
__device__ __forceinline__ void fma2(unsigned long long& a,
                                     unsigned long long x, unsigned long long d) {
    asm("fma.rn.f32x2 %0, %1, %2, %0;" : "+l"(a) : "l"(x), "l"(d));
}

__global__ __launch_bounds__(128, 8)
void softs_out_kernel(const float* __restrict__ X,
                      const float* __restrict__ tf,
                      float*       __restrict__ out)
{
    __shared__ float As[S_ * K_];   // 12.8 KB
    __shared__ float Tf[S_];
    __shared__ float Mk[K_], Ik[K_];

    const int b   = blockIdx.x;
    const int hb  = blockIdx.y;
    const int tid = threadIdx.x;

    for (int idx = tid; idx < S_ * K_; idx += 128)
        As[idx] = g_A[(size_t)b * S_ * K_ + idx];
    for (int idx = tid; idx < S_; idx += 128)
        Tf[idx] = tf[b * S_ + idx];
    __syncthreads();

    const int warp = tid >> 5, lane = tid & 31;
    for (int k = warp; k < K_; k += 4) {
        float m = -1e30f;
        for (int s = lane; s < S_; s += 32) m = fmaxf(m, As[s * K_ + k]);
        #pragma unroll
        for (int o = 16; o; o >>= 1) m = fmaxf(m, __shfl_xor_sync(0xffffffffu, m, o));
        float ssum = 0.0f;
        for (int s = lane; s < S_; s += 32) ssum += expf(As[s * K_ + k] - m);
        #pragma unroll
        for (int o = 16; o; o >>= 1) ssum += __shfl_xor_sync(0xffffffffu, ssum, o);
        if (lane == 0) { Mk[k] = m; Ik[k] = 1.0f / ssum; }
    }
    __syncthreads();

    for (int idx = tid; idx < S_ * K_; idx += 128) {
        const int s = idx >> 4, k = idx & 15;
        As[idx] = expf(As[idx] - Mk[k]) * Ik[k] * Tf[s];
    }
    __syncthreads();

    const int h = hb * 128 + tid;
    unsigned long long acc[8];
    #pragma unroll
    for (int i = 0; i < 8; i++) acc[i] = 0ull;

    const float* Xb = X + (size_t)b * S_ * H_ + h;
    #pragma unroll 4
    for (int s = 0; s < S_; s++) {
        const float xv = __ldg(Xb + (size_t)s * H_);
        unsigned long long xv2;
        asm("mov.b64 %0, {%1, %1};" : "=l"(xv2) : "f"(xv));
        const unsigned long long* d = (const unsigned long long*)&As[s * K_];
        #pragma unroll
        for (int i = 0; i < 8; i++) fma2(acc[i], xv2, d[i]);
    }

    float* ob = out + (size_t)b * K_ * H_ + h;
    #pragma unroll
    for (int i = 0; i < 8; i++) {
        float lo, hi;
        asm("mov.b64 {%0, %1}, %2;" : "=f"(lo), "=f"(hi) : "l"(acc[i]));
        ob[(size_t)(2 * i)     * H_] = lo;
        ob[(size_t)(2 * i + 1) * H_] = hi;
    }
}

// ---------------------------------------------------------------------------
extern "C" void kernel_launch(void* const* d_in, const int* in_sizes, int n_in,
                              void* d_out, int out_size)
{
    const float* X    = (const float*)d_in[0];   // (B,S,H)
    const int*   mask = (const int*)  d_in[1];   // (B,S,1)
    const float* tf   = (const float*)d_in[2];   // (B,S,1)
    const float* W1   = (const float*)d_in[3];
    const float* b1   = (const float*)d_in[4];
    const float* W2   = (const float*)d_in[5];
    const float* b2   = (const float*)d_in[6];
    const float* W3   = (const float*)d_in[7];
    float* out = (float*)d_out;                  // (B,K,H)

    cudaFuncSetAttribute(mlp_softk_kernel,
                         cudaFuncAttributeMaxDynamicSharedMemorySize, SM_BYTES);

    mlp_softk_kernel<<<NBLK, 256, SM_BYTES>>>(X, mask, W1, b1, W2, b2, W3);
    softs_out_kernel<<<dim3(B_, 2), 128>>>(X, tf, out);
}